// round 6
// baseline (speedup 1.0000x reference)
#include <cuda_runtime.h>
#include <cstdint>

// Problem constants (fixed shapes from setup_inputs)
#define TT 64
#define BB 4096
#define DD 32
#define HH 5
#define GG 20      // 4*H gates
#define VV 10
#define IN 128

#define BLK 256
#define IPT 2                       // items (b values) per thread
#define BPB (BLK * IPT)             // 512 b's per block
#define NCHUNK (BB / BPB)           // 8 b-chunks

// Per-b precomputed terms (transposed [g][B] for coalesced access), L2-resident.
__device__ float g_hb0[GG * BB];
__device__ float g_hb1[GG * BB];
__device__ float g_c0[HH * BB];
__device__ float g_c1[HH * BB];

__device__ __forceinline__ float sigm(float v) {
    return __fdividef(1.0f, 1.0f + __expf(-v));
}
__device__ __forceinline__ float tanh_(float v) {
    return 1.0f - __fdividef(2.0f, __expf(2.0f * v) + 1.0f);
}

// ---- packed f32x2 helpers (sm_103a FFMA2 path) ----
__device__ __forceinline__ unsigned long long pack2(float a, float b) {
    unsigned long long r;
    asm("mov.b64 %0, {%1, %2};" : "=l"(r) : "f"(a), "f"(b));
    return r;
}
__device__ __forceinline__ void unpack2(unsigned long long v, float& a, float& b) {
    asm("mov.b64 {%0, %1}, %2;" : "=f"(a), "=f"(b) : "l"(v));
}
__device__ __forceinline__ void ffma2(unsigned long long& d,
                                      unsigned long long a,
                                      unsigned long long b) {
    asm("fma.rn.f32x2 %0, %1, %2, %0;" : "+l"(d) : "l"(a), "l"(b));
}
__device__ __forceinline__ unsigned long long d2u(double d) {
    return (unsigned long long)__double_as_longlong(d);
}

// ---------------------------------------------------------------------------
// Kernel 1: per-b precompute of h@W_hh^T + biases, and cell transpose.
// ---------------------------------------------------------------------------
__global__ void prep_kernel(const float* __restrict__ hidden,
                            const float* __restrict__ cell,
                            const float* __restrict__ W_hh0,
                            const float* __restrict__ b_ih0,
                            const float* __restrict__ b_hh0,
                            const float* __restrict__ W_hh1,
                            const float* __restrict__ b_ih1,
                            const float* __restrict__ b_hh1) {
    int b = blockIdx.x * blockDim.x + threadIdx.x;
    if (b >= BB) return;

    float h0[HH], h1[HH];
#pragma unroll
    for (int k = 0; k < HH; k++) {
        h0[k] = hidden[b * HH + k];
        h1[k] = hidden[BB * HH + b * HH + k];
    }
#pragma unroll
    for (int g = 0; g < GG; g++) {
        float s0 = b_ih0[g] + b_hh0[g];
        float s1 = b_ih1[g] + b_hh1[g];
#pragma unroll
        for (int k = 0; k < HH; k++) {
            s0 = fmaf(h0[k], W_hh0[g * HH + k], s0);
            s1 = fmaf(h1[k], W_hh1[g * HH + k], s1);
        }
        g_hb0[g * BB + b] = s0;
        g_hb1[g * BB + b] = s1;
    }
#pragma unroll
    for (int k = 0; k < HH; k++) {
        g_c0[k * BB + b] = cell[b * HH + k];
        g_c1[k * BB + b] = cell[BB * HH + b * HH + k];
    }
}

// ---------------------------------------------------------------------------
// Kernel 2: main. One thread per (t, b-pair). Layer-0 GEMM uses packed
// f32x2 FMA with k-packing (register pairs come free from 128-bit loads).
// Layer-1 uses item-packing with (w,w)-duplicated shared weights.
//   blockIdx.x = b-chunk (8), blockIdx.y = t (64). 256 threads.
// ---------------------------------------------------------------------------
__global__ void __launch_bounds__(BLK)
decoder_kernel(const float* __restrict__ dec_x,
               const int*   __restrict__ id1,
               const int*   __restrict__ id2,
               const int*   __restrict__ id3,
               const float* __restrict__ embed,
               const float* __restrict__ W_ih0,
               const float* __restrict__ W_ih1,
               float* __restrict__ out) {
    __shared__ __align__(16) float sWa[GG * DD];        // W_ih0[:,0:32], 128B rows
    __shared__ __align__(16) float sLut[3 * VV * GG];   // [j][v][g]
    __shared__ __align__(16) float sW1d[HH * GG * 2];   // [k][g] -> (w,w) pairs
    __shared__ __align__(16) float sOut[BPB * HH];      // output staging

    const int tid = threadIdx.x;

    // ---- cooperative shared fill ----
    for (int i = tid; i < GG * DD; i += BLK) {
        int g = i >> 5, k = i & 31;
        sWa[i] = W_ih0[g * IN + k];
    }
    for (int i = tid; i < HH * GG; i += BLK) {
        int k = i / GG, g = i - k * GG;
        float w = W_ih1[g * HH + k];
        sW1d[2 * i] = w;
        sW1d[2 * i + 1] = w;
    }
    for (int i = tid; i < 3 * VV * GG; i += BLK) {
        int j = i / (VV * GG);
        int r = i - j * (VV * GG);
        int v = r / GG;
        int g = r - v * GG;
        const float* e = embed + v * DD;
        const float* w = W_ih0 + g * IN + DD + DD * j;
        float s = 0.0f;
#pragma unroll
        for (int k = 0; k < DD; k++) s = fmaf(e[k], w[k], s);
        sLut[i] = s;  // layout [j][v][g]
    }
    __syncthreads();

    const int t   = blockIdx.y;
    const int b0  = blockIdx.x * BPB + tid * IPT;   // even
    const int tb0 = t * BB + b0;

    // ================= layer-0 GEMM: packed along k ==================
    // acc2[it][g] holds (partial_even_k, partial_odd_k)
    unsigned long long acc2[IPT][GG];
#pragma unroll
    for (int it = 0; it < IPT; it++)
#pragma unroll
        for (int g = 0; g < GG; g++) acc2[it][g] = 0ULL;

    {
        const double2* xp0 = (const double2*)(dec_x + (size_t)tb0 * DD);
        const double2* xp1 = (const double2*)(dec_x + (size_t)(tb0 + 1) * DD);
#pragma unroll
        for (int q = 0; q < DD / 4; q++) {          // 4 k-values per q
            double2 x0 = xp0[q], x1 = xp1[q];
            unsigned long long x0a = d2u(x0.x), x0b = d2u(x0.y);
            unsigned long long x1a = d2u(x1.x), x1b = d2u(x1.y);
            const double2* wrow = (const double2*)(sWa + 4 * q);
#pragma unroll
            for (int g = 0; g < GG; g++) {
                double2 w = wrow[g * (DD / 4)];     // LDS.128: w[4q..4q+3]
                unsigned long long wa = d2u(w.x), wb = d2u(w.y);
                ffma2(acc2[0][g], x0a, wa);
                ffma2(acc2[0][g], x0b, wb);
                ffma2(acc2[1][g], x1a, wa);
                ffma2(acc2[1][g], x1b, wb);
            }
        }
    }

    // ---- horizontal sum + hb0 ----
    float hg[IPT][GG];
#pragma unroll
    for (int g = 0; g < GG; g++) {
        float2 v = *(const float2*)(g_hb0 + g * BB + b0);
        float lo, hi;
        unpack2(acc2[0][g], lo, hi);
        hg[0][g] = (lo + hi) + v.x;
        unpack2(acc2[1][g], lo, hi);
        hg[1][g] = (lo + hi) + v.y;
    }

    // ---- embedding LUT adds (f4 over g) ----
    {
        int2 iA = *(const int2*)(id1 + tb0);
        int2 iB = *(const int2*)(id2 + tb0);
        int2 iC = *(const int2*)(id3 + tb0);
        int ia[IPT] = {iA.x, iA.y};
        int ib[IPT] = {iB.x, iB.y};
        int ic[IPT] = {iC.x, iC.y};
#pragma unroll
        for (int it = 0; it < IPT; it++) {
            const float4* l1 = (const float4*)(sLut + (0 * VV + ia[it]) * GG);
            const float4* l2 = (const float4*)(sLut + (1 * VV + ib[it]) * GG);
            const float4* l3 = (const float4*)(sLut + (2 * VV + ic[it]) * GG);
#pragma unroll
            for (int q = 0; q < GG / 4; q++) {
                float4 a = l1[q], b = l2[q], c = l3[q];
                hg[it][4 * q + 0] += a.x + b.x + c.x;
                hg[it][4 * q + 1] += a.y + b.y + c.y;
                hg[it][4 * q + 2] += a.z + b.z + c.z;
                hg[it][4 * q + 3] += a.w + b.w + c.w;
            }
        }
    }

    // ---- LSTM cell 0 (gate order i, f, g, o) -> packed h1 pairs ----
    unsigned long long h2[HH];   // (h1_item0[k], h1_item1[k])
#pragma unroll
    for (int k = 0; k < HH; k++) {
        float2 c0 = *(const float2*)(g_c0 + k * BB + b0);
        float cc[IPT] = {c0.x, c0.y};
        float hv[IPT];
#pragma unroll
        for (int it = 0; it < IPT; it++) {
            float ig = sigm(hg[it][k]);
            float fg = sigm(hg[it][HH + k]);
            float gg = tanh_(hg[it][2 * HH + k]);
            float og = sigm(hg[it][3 * HH + k]);
            float c  = fmaf(fg, cc[it], ig * gg);
            hv[it] = og * tanh_(c);
        }
        h2[k] = pack2(hv[0], hv[1]);
    }

    // ---- layer 1 gates: packed across items ----
    unsigned long long a2[GG];
#pragma unroll
    for (int g = 0; g < GG; g++)
        a2[g] = *(const unsigned long long*)(g_hb1 + g * BB + b0);
#pragma unroll
    for (int k = 0; k < HH; k++) {
        const double2* wp = (const double2*)(sW1d + k * GG * 2);
#pragma unroll
        for (int q = 0; q < GG / 2; q++) {          // 2 gates per LDS.128
            double2 w = wp[q];
            ffma2(a2[2 * q + 0], h2[k], d2u(w.x));
            ffma2(a2[2 * q + 1], h2[k], d2u(w.y));
        }
    }

    // ---- LSTM cell 1 -> staged output ----
#pragma unroll
    for (int k = 0; k < HH; k++) {
        float2 c1 = *(const float2*)(g_c1 + k * BB + b0);
        float cc[IPT] = {c1.x, c1.y};
        float gi[IPT], gf[IPT], gc[IPT], go[IPT];
        unpack2(a2[k],          gi[0], gi[1]);
        unpack2(a2[HH + k],     gf[0], gf[1]);
        unpack2(a2[2 * HH + k], gc[0], gc[1]);
        unpack2(a2[3 * HH + k], go[0], go[1]);
#pragma unroll
        for (int it = 0; it < IPT; it++) {
            float ig = sigm(gi[it]);
            float fg = sigm(gf[it]);
            float gg = tanh_(gc[it]);
            float og = sigm(go[it]);
            float c  = fmaf(fg, cc[it], ig * gg);
            sOut[(tid * IPT + it) * HH + k] = og * tanh_(c);
        }
    }
    __syncthreads();

    // ---- coalesced store of the block's [512, 5] output slab ----
    float* ob = out + (size_t)t * BB * HH + (size_t)blockIdx.x * BPB * HH;
    for (int i = tid; i < BPB * HH; i += BLK) ob[i] = sOut[i];
}

// ---------------------------------------------------------------------------
// Launch
// Input order: 0 horizon, 1 hidden, 2 cell, 3 dec_x, 4 mote_id_cat,
// 5 fault_type_cat, 6 mote_fault_cat, 7 mote_embed, 8 W_ih0, 9 W_hh0,
// 10 b_ih0, 11 b_hh0, 12 W_ih1, 13 W_hh1, 14 b_ih1, 15 b_hh1
// ---------------------------------------------------------------------------
extern "C" void kernel_launch(void* const* d_in, const int* in_sizes, int n_in,
                              void* d_out, int out_size) {
    const float* hidden = (const float*)d_in[1];
    const float* cell   = (const float*)d_in[2];
    const float* dec_x  = (const float*)d_in[3];
    const int*   id1    = (const int*)d_in[4];
    const int*   id2    = (const int*)d_in[5];
    const int*   id3    = (const int*)d_in[6];
    const float* embed  = (const float*)d_in[7];
    const float* W_ih0  = (const float*)d_in[8];
    const float* W_hh0  = (const float*)d_in[9];
    const float* b_ih0  = (const float*)d_in[10];
    const float* b_hh0  = (const float*)d_in[11];
    const float* W_ih1  = (const float*)d_in[12];
    const float* W_hh1  = (const float*)d_in[13];
    const float* b_ih1  = (const float*)d_in[14];
    const float* b_hh1  = (const float*)d_in[15];
    float* out = (float*)d_out;

    prep_kernel<<<BB / BLK, BLK>>>(hidden, cell, W_hh0, b_ih0, b_hh0,
                                   W_hh1, b_ih1, b_hh1);

    dim3 grid(NCHUNK, TT);
    decoder_kernel<<<grid, BLK>>>(dec_x, id1, id2, id3, embed,
                                  W_ih0, W_ih1, out);
}